// round 4
// baseline (speedup 1.0000x reference)
#include <cuda_runtime.h>
#include <math.h>

typedef unsigned long long ull;

#define BB 128
#define TT 512
#define IND 64
#define HD 256
#define G3 768
#define LD 32
#define NPARD 1056
#define ODD 8

#define CL 4            // cluster size (K split of hidden dim)
#define NBAT 4          // batches per cluster
#define KS (HD/CL)      // 64 K-columns per CTA

// Scratch (static device arrays — no allocation allowed)
__device__ float g_gx[BB*TT*G3];    // 192 MB
__device__ float g_rnn[BB*TT*HD];   // 64 MB
__device__ float g_te[BB*TT*LD];    // 8 MB

__device__ __forceinline__ float sigm(float x){ return 1.0f/(1.0f+expf(-x)); }

// packed fp32 FMA (Blackwell f32x2) and horizontal add
__device__ __forceinline__ ull fma2(ull a, ull b, ull c){
    ull d;
    asm("fma.rn.f32x2 %0, %1, %2, %3;" : "=l"(d) : "l"(a), "l"(b), "l"(c));
    return d;
}
__device__ __forceinline__ float hadd2(ull a){
    unsigned lo, hi;
    asm("mov.b64 {%0,%1}, %2;" : "=r"(lo), "=r"(hi) : "l"(a));
    return __uint_as_float(lo) + __uint_as_float(hi);
}

// ------------------------------------------------------------------
// K1: gx[bt,g] = x[bt,:] . w_ih[g,:] + b_ih[g]   (R2 version)
// ------------------------------------------------------------------
__global__ __launch_bounds__(256) void k_gx(const float* __restrict__ x,
                                            const float* __restrict__ w_ih,
                                            const float* __restrict__ b_ih)
{
    __shared__ float xs[64][65];
    __shared__ float ws[64][65];
    int m0 = blockIdx.y * 64;
    int n0 = blockIdx.x * 64;
    int tid = threadIdx.y * 16 + threadIdx.x;
    const float4* x4 = (const float4*)x;
    const float4* w4 = (const float4*)w_ih;
    for (int q = tid; q < 1024; q += 256) {
        int row = q >> 4, c4 = q & 15;
        float4 v = x4[(size_t)(m0 + row) * 16 + c4];
        xs[row][c4*4+0] = v.x; xs[row][c4*4+1] = v.y;
        xs[row][c4*4+2] = v.z; xs[row][c4*4+3] = v.w;
        float4 wv = w4[(size_t)(n0 + row) * 16 + c4];
        ws[row][c4*4+0] = wv.x; ws[row][c4*4+1] = wv.y;
        ws[row][c4*4+2] = wv.z; ws[row][c4*4+3] = wv.w;
    }
    __syncthreads();
    int tr = threadIdx.y * 4, tc = threadIdx.x * 4;
    float acc[4][4] = {};
    #pragma unroll 8
    for (int k = 0; k < 64; k++) {
        float av[4], bv[4];
        #pragma unroll
        for (int i = 0; i < 4; i++) av[i] = xs[tr + i][k];
        #pragma unroll
        for (int j = 0; j < 4; j++) bv[j] = ws[tc + j][k];
        #pragma unroll
        for (int i = 0; i < 4; i++)
            #pragma unroll
            for (int j = 0; j < 4; j++)
                acc[i][j] = fmaf(av[i], bv[j], acc[i][j]);
    }
    float b0 = b_ih[n0+tc+0], b1 = b_ih[n0+tc+1], b2 = b_ih[n0+tc+2], b3 = b_ih[n0+tc+3];
    #pragma unroll
    for (int i = 0; i < 4; i++) {
        float4 o;
        o.x = acc[i][0] + b0; o.y = acc[i][1] + b1;
        o.z = acc[i][2] + b2; o.w = acc[i][3] + b3;
        *(float4*)&g_gx[(size_t)(m0 + tr + i) * G3 + n0 + tc] = o;
    }
}

// ------------------------------------------------------------------
// K2: GRU recurrence (R2 version): cluster of 4 CTAs, w_hh in regs.
// ------------------------------------------------------------------
__global__ __launch_bounds__(G3, 1) __cluster_dims__(CL, 1, 1)
void k_gru(const float* __restrict__ hidden,
           const float* __restrict__ w_hh,
           const float* __restrict__ b_hh,
           float* __restrict__ hT)
{
    __shared__ float4 hs4[NBAT][KS/4];          // local hidden slice, 4 x 64
    __shared__ float pbuf[2][CL][NBAT][192];    // partial sums, double-buffered
    int tid = threadIdx.x;
    unsigned rank;
    asm("mov.u32 %0, %%cluster_ctarank;" : "=r"(rank));
    int b0 = (blockIdx.x / CL) * NBAT;

    // weight slice into registers: row = tid, k in [KS*rank, KS*(rank+1))
    float4 w[KS/4];
    {
        const float4* wsrc = (const float4*)(w_hh + (size_t)tid * HD + KS * rank);
        #pragma unroll
        for (int i = 0; i < KS/4; i++) w[i] = wsrc[i];
    }

    float* hs = (float*)hs4;
    int gb = tid >> 6, gj = tid & 63;           // gate-thread coords (tid<256)
    int hidx = KS * (int)rank + gj;
    float bh_r = 0.f, bh_z = 0.f, bh_n = 0.f;
    if (tid < NBAT * KS) {
        hs[gb * KS + gj] = hidden[(size_t)(b0 + gb) * HD + hidx];
        bh_r = b_hh[hidx]; bh_z = b_hh[HD + hidx]; bh_n = b_hh[2*HD + hidx];
    }

    // partial routing: row r=tid -> dest CTA=(r&255)>>6, slot=(r>>8)*64+(r&63)
    int dest = (tid & 255) >> 6;
    int slot = (tid >> 8) * 64 + (tid & 63);
    unsigned raddr0, raddr1;
    {
        unsigned la0 = (unsigned)__cvta_generic_to_shared(&pbuf[0][rank][0][slot]);
        unsigned la1 = (unsigned)__cvta_generic_to_shared(&pbuf[1][rank][0][slot]);
        asm("mapa.shared::cluster.u32 %0, %1, %2;" : "=r"(raddr0) : "r"(la0), "r"(dest));
        asm("mapa.shared::cluster.u32 %0, %1, %2;" : "=r"(raddr1) : "r"(la1), "r"(dest));
    }
    __syncthreads();

    for (int t = 0; t < TT; t++) {
        // prefetch gx (long-scoreboard covered by FMA block below)
        float xr = 0.f, xz = 0.f, xn = 0.f;
        if (tid < NBAT * KS) {
            const float* gxp = g_gx + ((size_t)(b0 + gb) * TT + t) * G3;
            xr = gxp[hidx]; xz = gxp[HD + hidx]; xn = gxp[2*HD + hidx];
        }
        // partial gh for 4 batches over local K slice (w in regs, h broadcast LDS)
        float a0 = 0.f, a1 = 0.f, a2 = 0.f, a3 = 0.f;
        #pragma unroll
        for (int k = 0; k < KS/4; k++) {
            float4 wv = w[k];
            float4 h0 = hs4[0][k];
            a0 = fmaf(wv.x,h0.x,a0); a0 = fmaf(wv.y,h0.y,a0);
            a0 = fmaf(wv.z,h0.z,a0); a0 = fmaf(wv.w,h0.w,a0);
            float4 h1 = hs4[1][k];
            a1 = fmaf(wv.x,h1.x,a1); a1 = fmaf(wv.y,h1.y,a1);
            a1 = fmaf(wv.z,h1.z,a1); a1 = fmaf(wv.w,h1.w,a1);
            float4 h2 = hs4[2][k];
            a2 = fmaf(wv.x,h2.x,a2); a2 = fmaf(wv.y,h2.y,a2);
            a2 = fmaf(wv.z,h2.z,a2); a2 = fmaf(wv.w,h2.w,a2);
            float4 h3 = hs4[3][k];
            a3 = fmaf(wv.x,h3.x,a3); a3 = fmaf(wv.y,h3.y,a3);
            a3 = fmaf(wv.z,h3.z,a3); a3 = fmaf(wv.w,h3.w,a3);
        }
        // ship partials to owning CTA (batch stride = 192 floats = 768 B)
        unsigned ra = (t & 1) ? raddr1 : raddr0;
        asm volatile("st.shared::cluster.f32 [%0], %1;" :: "r"(ra),         "f"(a0));
        asm volatile("st.shared::cluster.f32 [%0], %1;" :: "r"(ra + 768u),  "f"(a1));
        asm volatile("st.shared::cluster.f32 [%0], %1;" :: "r"(ra + 1536u), "f"(a2));
        asm volatile("st.shared::cluster.f32 [%0], %1;" :: "r"(ra + 2304u), "f"(a3));
        asm volatile("barrier.cluster.arrive.aligned;" ::: "memory");
        asm volatile("barrier.cluster.wait.aligned;"   ::: "memory");
        // gate phase: combine 4 partials per gate, update local h slice
        if (tid < NBAT * KS) {
            int buf = t & 1;
            float hr = pbuf[buf][0][gb][gj]     + pbuf[buf][1][gb][gj]
                     + pbuf[buf][2][gb][gj]     + pbuf[buf][3][gb][gj]     + bh_r;
            float hz = pbuf[buf][0][gb][64+gj]  + pbuf[buf][1][gb][64+gj]
                     + pbuf[buf][2][gb][64+gj]  + pbuf[buf][3][gb][64+gj]  + bh_z;
            float hn = pbuf[buf][0][gb][128+gj] + pbuf[buf][1][gb][128+gj]
                     + pbuf[buf][2][gb][128+gj] + pbuf[buf][3][gb][128+gj] + bh_n;
            float r = sigm(xr + hr);
            float z = sigm(xz + hz);
            float n = tanhf(xn + r * hn);
            float hp = hs[gb*KS + gj];
            float hnew = (1.0f - z) * n + z * hp;
            hs[gb*KS + gj] = hnew;
            g_rnn[((size_t)(b0 + gb) * TT + t) * HD + hidx] = hnew;
        }
        __syncthreads();
    }
    if (tid < NBAT * KS) hT[(size_t)(b0 + gb) * HD + hidx] = hs[gb*KS + gj];
}

// ------------------------------------------------------------------
// K3a: task_enc[bt,l] = rnn[bt,:] . w_lat[l,:] + b_lat[l]  (R2 version)
// ------------------------------------------------------------------
__global__ __launch_bounds__(256) void k_te(const float* __restrict__ w_lat,
                                            const float* __restrict__ b_lat)
{
    __shared__ float4 rows4[32 * 64];
    int tid = threadIdx.x;
    int bt0 = blockIdx.x * 32;
    const float4* rnn4 = (const float4*)g_rnn;
    for (int q = tid; q < 2048; q += 256) rows4[q] = rnn4[(size_t)bt0 * 64 + q];
    __syncthreads();
    int pair = tid >> 3;
    int l0 = (tid & 7) * 4;
    const float4* wl4 = (const float4*)w_lat;
    float acc[4];
    #pragma unroll
    for (int j = 0; j < 4; j++) acc[j] = b_lat[l0 + j];
    #pragma unroll 8
    for (int k4 = 0; k4 < 64; k4++) {
        float4 r = rows4[pair * 64 + k4];
        #pragma unroll
        for (int j = 0; j < 4; j++) {
            float4 w = wl4[(size_t)(l0 + j) * 64 + k4];
            acc[j] = fmaf(r.x, w.x, acc[j]);
            acc[j] = fmaf(r.y, w.y, acc[j]);
            acc[j] = fmaf(r.z, w.z, acc[j]);
            acc[j] = fmaf(r.w, w.w, acc[j]);
        }
    }
    float4 o = {acc[0], acc[1], acc[2], acc[3]};
    *(float4*)&g_te[(size_t)(bt0 + pair) * LD + l0] = o;
}

// ------------------------------------------------------------------
// K3b: fused params GEMM (K=32, f32x2) + hyper-MLP. 16 bt per block.
// (R3 version — regs 128, all-256-thread phases, dynamic smem)
// ------------------------------------------------------------------
#define PAIRS 16
#define TAIL_SMEM (PAIRS*16*8 + PAIRS*48*4 + PAIRS*NPARD*4 + PAIRS*16*4)
__global__ __launch_bounds__(256) void k_tail(const float* __restrict__ x,
                                              const float* __restrict__ w_par,
                                              const float* __restrict__ b_par,
                                              float* __restrict__ out_mean,
                                              float* __restrict__ out_std)
{
    extern __shared__ char smem[];
    ull*   te2  = (ull*)smem;                          // [16][16]
    float* st_s = (float*)(smem + PAIRS*16*8);         // [16][48]
    float* ps   = st_s + PAIRS*48;                     // [16][1056]
    float* hid  = ps + PAIRS*NPARD;                    // [16][16]

    int tid = threadIdx.x;
    int bt0 = blockIdx.x * PAIRS;

    // load task_enc (16 bt x 32 floats) as f32x2 pairs
    if (tid < PAIRS * 8) {
        int p = tid >> 3, q = tid & 7;
        ulonglong2 v = ((const ulonglong2*)g_te)[(size_t)(bt0 + p) * 8 + q];
        te2[p*16 + q*2]     = v.x;
        te2[p*16 + q*2 + 1] = v.y;
    }
    // load states (first 48 of 64 input dims), keep 16B alignment per row
    for (int q = tid; q < PAIRS * 12; q += 256) {
        int p = q / 12, c = q % 12;
        ((float4*)st_s)[p*12 + c] = ((const float4*)x)[(size_t)(bt0 + p) * 16 + c];
    }
    __syncthreads();

    // phase 1: params = b_par + w_par @ te  (per bt), f32x2 over l
    for (int idx = tid; idx < NPARD; idx += 256) {
        ull wrow[16];
        const ulonglong2* wp = (const ulonglong2*)(w_par + (size_t)idx * 32);
        #pragma unroll
        for (int q = 0; q < 8; q++) { ulonglong2 v = wp[q]; wrow[2*q] = v.x; wrow[2*q+1] = v.y; }
        float bp = b_par[idx];
        ull acc[PAIRS] = {};
        #pragma unroll
        for (int l2 = 0; l2 < 16; l2++) {
            ull wv = wrow[l2];
            #pragma unroll
            for (int p = 0; p < PAIRS; p++)
                acc[p] = fma2(wv, te2[p*16 + l2], acc[p]);
        }
        #pragma unroll
        for (int p = 0; p < PAIRS; p++) ps[p * NPARD + idx] = hadd2(acc[p]) + bp;
    }
    __syncthreads();

    // phase 2: out_hidden[pair][p] = tanh(w_h[p,:] . state + b_h[p])
    {
        int pair = tid >> 4, p = tid & 15;
        const float4* wh4 = (const float4*)(ps + pair * NPARD + p * 48);
        const float4* st4 = (const float4*)(st_s + pair * 48);
        float a = ps[pair * NPARD + 768 + p];
        #pragma unroll
        for (int q = 0; q < 12; q++) {
            float4 wv = wh4[q];
            float4 sv = st4[q];
            a = fmaf(wv.x, sv.x, a); a = fmaf(wv.y, sv.y, a);
            a = fmaf(wv.z, sv.z, a); a = fmaf(wv.w, sv.w, a);
        }
        hid[pair*16 + p] = tanhf(a);
    }
    __syncthreads();

    // phase 3: mlp[pair][o] = w_o[o,:] . hidden + b_o[o]
    {
        int pair = tid >> 4, o = tid & 15;
        const float4* wo4 = (const float4*)(ps + pair * NPARD + 784 + o * 16);
        const float4* hv4 = (const float4*)(hid + pair * 16);
        float m = ps[pair * NPARD + 1040 + o];
        #pragma unroll
        for (int q = 0; q < 4; q++) {
            float4 wv = wo4[q];
            float4 hv = hv4[q];
            m = fmaf(wv.x, hv.x, m); m = fmaf(wv.y, hv.y, m);
            m = fmaf(wv.z, hv.z, m); m = fmaf(wv.w, hv.w, m);
        }
        size_t bt = bt0 + pair;
        if (o < 8) out_mean[bt * ODD + o] = m;
        else       out_std[bt * ODD + (o - 8)] = expf(m);
    }
}

// ------------------------------------------------------------------
extern "C" void kernel_launch(void* const* d_in, const int* in_sizes, int n_in,
                              void* d_out, int out_size)
{
    const float* x      = (const float*)d_in[0];
    const float* hidden = (const float*)d_in[1];
    const float* w_ih   = (const float*)d_in[2];
    const float* w_hh   = (const float*)d_in[3];
    const float* b_ih   = (const float*)d_in[4];
    const float* b_hh   = (const float*)d_in[5];
    const float* w_lat  = (const float*)d_in[6];
    const float* b_lat  = (const float*)d_in[7];
    const float* w_par  = (const float*)d_in[8];
    const float* b_par  = (const float*)d_in[9];
    (void)in_sizes; (void)n_in; (void)out_size;

    float* out      = (float*)d_out;
    float* out_mean = out;                                  // B*T*8
    float* out_std  = out + (size_t)BB * TT * ODD;          // B*T*8
    float* out_hT   = out + (size_t)2 * BB * TT * ODD;      // B*256

    cudaFuncSetAttribute(k_tail, cudaFuncAttributeMaxDynamicSharedMemorySize, TAIL_SMEM);

    dim3 g1(G3 / 64, (BB * TT) / 64), b1(16, 16);
    k_gx  <<<g1, b1>>>(x, w_ih, b_ih);
    k_gru <<<(BB / NBAT) * CL, G3>>>(hidden, w_hh, b_hh, out_hT);
    k_te  <<<(BB * TT) / 32, 256>>>(w_lat, b_lat);
    k_tail<<<(BB * TT) / PAIRS, 256, TAIL_SMEM>>>(x, w_par, b_par, out_mean, out_std);
}

// round 5
// speedup vs baseline: 1.2316x; 1.2316x over previous
#include <cuda_runtime.h>
#include <math.h>

typedef unsigned long long ull;

#define BB 128
#define TT 512
#define IND 64
#define HD 256
#define G3 768
#define LD 32
#define NPARD 1056
#define ODD 8

#define CL 4            // cluster size (K split of hidden dim)
#define NBAT 4          // batches per cluster
#define KS (HD/CL)      // 64 K-columns per CTA

// Scratch (static device arrays — no allocation allowed)
__device__ float g_gx[BB*TT*G3];    // 192 MB
__device__ float g_rnn[BB*TT*HD];   // 64 MB
__device__ float g_te[BB*TT*LD];    // 8 MB

__device__ __forceinline__ float sigm(float x){ return 1.0f/(1.0f+expf(-x)); }

// packed fp32 FMA (Blackwell f32x2) and horizontal add
__device__ __forceinline__ ull fma2(ull a, ull b, ull c){
    ull d;
    asm("fma.rn.f32x2 %0, %1, %2, %3;" : "=l"(d) : "l"(a), "l"(b), "l"(c));
    return d;
}
__device__ __forceinline__ float hadd2(ull a){
    unsigned lo, hi;
    asm("mov.b64 {%0,%1}, %2;" : "=r"(lo), "=r"(hi) : "l"(a));
    return __uint_as_float(lo) + __uint_as_float(hi);
}

// ------------------------------------------------------------------
// K1: gx[bt,g] = x[bt,:] . w_ih[g,:] + b_ih[g]   (f32x2 microkernel)
// ------------------------------------------------------------------
__global__ __launch_bounds__(256) void k_gx(const float* __restrict__ x,
                                            const float* __restrict__ w_ih,
                                            const float* __restrict__ b_ih)
{
    __shared__ float2 xs[64][33];
    __shared__ float2 ws[64][33];
    int m0 = blockIdx.y * 64;
    int n0 = blockIdx.x * 64;
    int tid = threadIdx.y * 16 + threadIdx.x;
    const float4* x4 = (const float4*)x;
    const float4* w4 = (const float4*)w_ih;
    for (int q = tid; q < 1024; q += 256) {
        int row = q >> 4, c4 = q & 15;
        float4 v = x4[(size_t)(m0 + row) * 16 + c4];
        xs[row][c4*2+0] = make_float2(v.x, v.y);
        xs[row][c4*2+1] = make_float2(v.z, v.w);
        float4 wv = w4[(size_t)(n0 + row) * 16 + c4];
        ws[row][c4*2+0] = make_float2(wv.x, wv.y);
        ws[row][c4*2+1] = make_float2(wv.z, wv.w);
    }
    __syncthreads();
    int tr = threadIdx.y * 4, tc = threadIdx.x * 4;
    ull acc[4][4] = {};
    #pragma unroll 8
    for (int k2 = 0; k2 < 32; k2++) {
        ull av[4], bv[4];
        #pragma unroll
        for (int i = 0; i < 4; i++) av[i] = *(const ull*)&xs[tr + i][k2];
        #pragma unroll
        for (int j = 0; j < 4; j++) bv[j] = *(const ull*)&ws[tc + j][k2];
        #pragma unroll
        for (int i = 0; i < 4; i++)
            #pragma unroll
            for (int j = 0; j < 4; j++)
                acc[i][j] = fma2(av[i], bv[j], acc[i][j]);
    }
    float b0 = b_ih[n0+tc+0], b1 = b_ih[n0+tc+1], b2 = b_ih[n0+tc+2], b3 = b_ih[n0+tc+3];
    #pragma unroll
    for (int i = 0; i < 4; i++) {
        float4 o;
        o.x = hadd2(acc[i][0]) + b0; o.y = hadd2(acc[i][1]) + b1;
        o.z = hadd2(acc[i][2]) + b2; o.w = hadd2(acc[i][3]) + b3;
        *(float4*)&g_gx[(size_t)(m0 + tr + i) * G3 + n0 + tc] = o;
    }
}

// ------------------------------------------------------------------
// K2: GRU recurrence, cluster of 4 CTAs (K split), w_hh in registers.
// f32x2 FMA; h via LDS.128 bit-cast; gx prefetched with plain LDG.
// ------------------------------------------------------------------
__global__ __launch_bounds__(G3, 1) __cluster_dims__(CL, 1, 1)
void k_gru(const float* __restrict__ hidden,
           const float* __restrict__ w_hh,
           const float* __restrict__ b_hh,
           float* __restrict__ hT)
{
    __shared__ float4 hs4[NBAT][KS/4];          // local hidden slice, 4 x 64
    __shared__ float pbuf[2][CL][NBAT][192];    // partial sums, double-buffered
    int tid = threadIdx.x;
    unsigned rank;
    asm("mov.u32 %0, %%cluster_ctarank;" : "=r"(rank));
    int b0 = (blockIdx.x / CL) * NBAT;

    // weight slice into registers: row = tid, k in [KS*rank, KS*(rank+1))
    float4 w[KS/4];
    {
        const float4* wsrc = (const float4*)(w_hh + (size_t)tid * HD + KS * rank);
        #pragma unroll
        for (int i = 0; i < KS/4; i++) w[i] = wsrc[i];
    }

    float* hs = (float*)hs4;
    int gb = tid >> 6, gj = tid & 63;           // gate-thread coords (tid<256)
    int hidx = KS * (int)rank + gj;
    float bh_r = 0.f, bh_z = 0.f, bh_n = 0.f;
    if (tid < NBAT * KS) {
        hs[gb * KS + gj] = hidden[(size_t)(b0 + gb) * HD + hidx];
        bh_r = b_hh[hidx]; bh_z = b_hh[HD + hidx]; bh_n = b_hh[2*HD + hidx];
    }

    // partial routing: row r=tid -> dest CTA=(r&255)>>6, slot=(r>>8)*64+(r&63)
    int dest = (tid & 255) >> 6;
    int slot = (tid >> 8) * 64 + (tid & 63);
    unsigned raddr0, raddr1;
    {
        unsigned la0 = (unsigned)__cvta_generic_to_shared(&pbuf[0][rank][0][slot]);
        unsigned la1 = (unsigned)__cvta_generic_to_shared(&pbuf[1][rank][0][slot]);
        asm("mapa.shared::cluster.u32 %0, %1, %2;" : "=r"(raddr0) : "r"(la0), "r"(dest));
        asm("mapa.shared::cluster.u32 %0, %1, %2;" : "=r"(raddr1) : "r"(la1), "r"(dest));
    }
    __syncthreads();

    for (int t = 0; t < TT; t++) {
        // prefetch gx (long-scoreboard covered by FMA block below)
        float xr = 0.f, xz = 0.f, xn = 0.f;
        if (tid < NBAT * KS) {
            const float* gxp = g_gx + ((size_t)(b0 + gb) * TT + t) * G3;
            xr = gxp[hidx]; xz = gxp[HD + hidx]; xn = gxp[2*HD + hidx];
        }
        // partial gh for 4 batches over local K slice (f32x2, LDS.128 h)
        ull a0 = 0ull, a1 = 0ull, a2 = 0ull, a3 = 0ull;
        #pragma unroll
        for (int k = 0; k < KS/4; k++) {
            float4 wv = w[k];
            ull w01 = *(const ull*)&wv.x;
            ull w23 = *(const ull*)&wv.z;
            float4 h0 = hs4[0][k];
            a0 = fma2(w01, *(const ull*)&h0.x, a0);
            a0 = fma2(w23, *(const ull*)&h0.z, a0);
            float4 h1 = hs4[1][k];
            a1 = fma2(w01, *(const ull*)&h1.x, a1);
            a1 = fma2(w23, *(const ull*)&h1.z, a1);
            float4 h2 = hs4[2][k];
            a2 = fma2(w01, *(const ull*)&h2.x, a2);
            a2 = fma2(w23, *(const ull*)&h2.z, a2);
            float4 h3 = hs4[3][k];
            a3 = fma2(w01, *(const ull*)&h3.x, a3);
            a3 = fma2(w23, *(const ull*)&h3.z, a3);
        }
        float s0 = hadd2(a0), s1 = hadd2(a1), s2 = hadd2(a2), s3 = hadd2(a3);

        // ship partials to owning CTA (batch stride = 192 floats = 768 B)
        unsigned ra = (t & 1) ? raddr1 : raddr0;
        asm volatile("st.shared::cluster.f32 [%0], %1;" :: "r"(ra),         "f"(s0));
        asm volatile("st.shared::cluster.f32 [%0], %1;" :: "r"(ra + 768u),  "f"(s1));
        asm volatile("st.shared::cluster.f32 [%0], %1;" :: "r"(ra + 1536u), "f"(s2));
        asm volatile("st.shared::cluster.f32 [%0], %1;" :: "r"(ra + 2304u), "f"(s3));
        asm volatile("barrier.cluster.arrive.aligned;" ::: "memory");
        asm volatile("barrier.cluster.wait.aligned;"   ::: "memory");

        // gate phase: combine 4 partials per gate, update local h slice
        if (tid < NBAT * KS) {
            int buf = t & 1;
            float hr = pbuf[buf][0][gb][gj]     + pbuf[buf][1][gb][gj]
                     + pbuf[buf][2][gb][gj]     + pbuf[buf][3][gb][gj]     + bh_r;
            float hz = pbuf[buf][0][gb][64+gj]  + pbuf[buf][1][gb][64+gj]
                     + pbuf[buf][2][gb][64+gj]  + pbuf[buf][3][gb][64+gj]  + bh_z;
            float hn = pbuf[buf][0][gb][128+gj] + pbuf[buf][1][gb][128+gj]
                     + pbuf[buf][2][gb][128+gj] + pbuf[buf][3][gb][128+gj] + bh_n;
            float r = sigm(xr + hr);
            float z = sigm(xz + hz);
            float n = tanhf(xn + r * hn);
            float hp = hs[gb*KS + gj];
            float hnew = (1.0f - z) * n + z * hp;
            hs[gb*KS + gj] = hnew;
            g_rnn[((size_t)(b0 + gb) * TT + t) * HD + hidx] = hnew;
        }
        __syncthreads();
    }
    if (tid < NBAT * KS) hT[(size_t)(b0 + gb) * HD + hidx] = hs[gb*KS + gj];
}

// ------------------------------------------------------------------
// K3a: task_enc[bt,l] = rnn[bt,:] . w_lat[l,:] + b_lat[l]  (f32x2)
// ------------------------------------------------------------------
__global__ __launch_bounds__(256) void k_te(const float* __restrict__ w_lat,
                                            const float* __restrict__ b_lat)
{
    __shared__ ulonglong2 rows4[32 * 64];
    int tid = threadIdx.x;
    int bt0 = blockIdx.x * 32;
    const ulonglong2* rnn4 = (const ulonglong2*)g_rnn;
    for (int q = tid; q < 2048; q += 256) rows4[q] = rnn4[(size_t)bt0 * 64 + q];
    __syncthreads();
    int pair = tid >> 3;
    int l0 = (tid & 7) * 4;
    const ulonglong2* wl4 = (const ulonglong2*)w_lat;
    ull acc[4] = {};
    #pragma unroll 8
    for (int k4 = 0; k4 < 64; k4++) {
        ulonglong2 r = rows4[pair * 64 + k4];
        #pragma unroll
        for (int j = 0; j < 4; j++) {
            ulonglong2 wv = wl4[(size_t)(l0 + j) * 64 + k4];
            acc[j] = fma2(r.x, wv.x, acc[j]);
            acc[j] = fma2(r.y, wv.y, acc[j]);
        }
    }
    float4 o;
    o.x = hadd2(acc[0]) + b_lat[l0+0];
    o.y = hadd2(acc[1]) + b_lat[l0+1];
    o.z = hadd2(acc[2]) + b_lat[l0+2];
    o.w = hadd2(acc[3]) + b_lat[l0+3];
    *(float4*)&g_te[(size_t)(bt0 + pair) * LD + l0] = o;
}

// ------------------------------------------------------------------
// K3b: fused params GEMM (K=32, f32x2) + hyper-MLP. 8 bt per block,
// STATIC smem (~37KB), #pragma unroll 1 on idx loop (reg control).
// ------------------------------------------------------------------
#define PAIRS 8
__global__ __launch_bounds__(256) void k_tail(const float* __restrict__ x,
                                              const float* __restrict__ w_par,
                                              const float* __restrict__ b_par,
                                              float* __restrict__ out_mean,
                                              float* __restrict__ out_std)
{
    __shared__ ull   te2[PAIRS][16];       // task_enc as f32x2 pairs
    __shared__ float st_s[PAIRS][48];      // states (16B-aligned rows)
    __shared__ float ps[PAIRS * NPARD];    // generated params
    __shared__ float hid[PAIRS][16];
    int tid = threadIdx.x;
    int bt0 = blockIdx.x * PAIRS;

    if (tid < PAIRS * 8) {
        int p = tid >> 3, q = tid & 7;
        ulonglong2 v = ((const ulonglong2*)g_te)[(size_t)(bt0 + p) * 8 + q];
        te2[p][q*2]     = v.x;
        te2[p][q*2 + 1] = v.y;
    }
    if (tid < PAIRS * 12) {
        int p = tid / 12, c = tid % 12;
        ((float4*)&st_s[p][0])[c] = ((const float4*)x)[(size_t)(bt0 + p) * 16 + c];
    }
    __syncthreads();

    // phase 1: params = b_par + w_par @ te  (f32x2 over l)
    #pragma unroll 1
    for (int idx = tid; idx < NPARD; idx += 256) {
        const ulonglong2* wp = (const ulonglong2*)(w_par + (size_t)idx * 32);
        ull acc[PAIRS] = {};
        #pragma unroll
        for (int q = 0; q < 8; q++) {
            ulonglong2 wv = wp[q];
            #pragma unroll
            for (int p = 0; p < PAIRS; p++) {
                acc[p] = fma2(wv.x, te2[p][q*2],     acc[p]);
                acc[p] = fma2(wv.y, te2[p][q*2 + 1], acc[p]);
            }
        }
        float bp = b_par[idx];
        #pragma unroll
        for (int p = 0; p < PAIRS; p++) ps[p * NPARD + idx] = hadd2(acc[p]) + bp;
    }
    __syncthreads();

    // phase 2: out_hidden[pair][p] = tanh(w_h[p,:] . state + b_h[p])
    if (tid < PAIRS * 16) {
        int pair = tid >> 4, p = tid & 15;
        const float4* wh4 = (const float4*)(ps + pair * NPARD + p * 48);
        const float4* st4 = (const float4*)&st_s[pair][0];
        float a = ps[pair * NPARD + 768 + p];
        #pragma unroll
        for (int q = 0; q < 12; q++) {
            float4 wv = wh4[q];
            float4 sv = st4[q];
            a = fmaf(wv.x, sv.x, a); a = fmaf(wv.y, sv.y, a);
            a = fmaf(wv.z, sv.z, a); a = fmaf(wv.w, sv.w, a);
        }
        hid[pair][p] = tanhf(a);
    }
    __syncthreads();

    // phase 3: mlp[pair][o] = w_o[o,:] . hidden + b_o[o]
    if (tid < PAIRS * 16) {
        int pair = tid >> 4, o = tid & 15;
        const float4* wo4 = (const float4*)(ps + pair * NPARD + 784 + o * 16);
        const float4* hv4 = (const float4*)&hid[pair][0];
        float m = ps[pair * NPARD + 1040 + o];
        #pragma unroll
        for (int q = 0; q < 4; q++) {
            float4 wv = wo4[q];
            float4 hv = hv4[q];
            m = fmaf(wv.x, hv.x, m); m = fmaf(wv.y, hv.y, m);
            m = fmaf(wv.z, hv.z, m); m = fmaf(wv.w, hv.w, m);
        }
        size_t bt = bt0 + pair;
        if (o < 8) out_mean[bt * ODD + o] = m;
        else       out_std[bt * ODD + (o - 8)] = expf(m);
    }
}

// ------------------------------------------------------------------
extern "C" void kernel_launch(void* const* d_in, const int* in_sizes, int n_in,
                              void* d_out, int out_size)
{
    const float* x      = (const float*)d_in[0];
    const float* hidden = (const float*)d_in[1];
    const float* w_ih   = (const float*)d_in[2];
    const float* w_hh   = (const float*)d_in[3];
    const float* b_ih   = (const float*)d_in[4];
    const float* b_hh   = (const float*)d_in[5];
    const float* w_lat  = (const float*)d_in[6];
    const float* b_lat  = (const float*)d_in[7];
    const float* w_par  = (const float*)d_in[8];
    const float* b_par  = (const float*)d_in[9];
    (void)in_sizes; (void)n_in; (void)out_size;

    float* out      = (float*)d_out;
    float* out_mean = out;                                  // B*T*8
    float* out_std  = out + (size_t)BB * TT * ODD;          // B*T*8
    float* out_hT   = out + (size_t)2 * BB * TT * ODD;      // B*256

    dim3 g1(G3 / 64, (BB * TT) / 64), b1(16, 16);
    k_gx  <<<g1, b1>>>(x, w_ih, b_ih);
    k_gru <<<(BB / NBAT) * CL, G3>>>(hidden, w_hh, b_hh, out_hT);
    k_te  <<<(BB * TT) / 32, 256>>>(w_lat, b_lat);
    k_tail<<<(BB * TT) / PAIRS, 256>>>(x, w_par, b_par, out_mean, out_std);
}